// round 1
// baseline (speedup 1.0000x reference)
#include <cuda_runtime.h>
#include <cuda_bf16.h>

#define NN 100000
#define EE 1600000
#define IN_F 256
#define HH 4
#define CC 32
#define HC 128   // HH*CC

// ---------------- device scratch (no allocations allowed) ----------------
__device__ float g_feat[NN * HC];   // projected features [N, H*C]
__device__ float g_el[NN * HH];     // left attention logits
__device__ float g_er[NN * HH];     // right attention logits
__device__ float g_ex[(size_t)EE * HH];   // exp(e) per edge
__device__ float g_s[NN * HH];      // softmax denominators
__device__ float g_acc[NN * HC];    // aggregated output accumulator

// ---------------- kernel 1: feat = x @ W, fused el/er epilogue ----------------
// BM=64, BN=128(all cols), BK=32. 256 threads: tx in [0,32) owns 4 cols, ty in
// [0,8) owns 8 rows. Epilogue: per-row segmented (8-lane) shfl reduction gives
// el/er per (row, head) without re-reading feat.
__global__ __launch_bounds__(256) void gemm_feat_kernel(
    const float* __restrict__ x, const float* __restrict__ W,
    const float* __restrict__ attn_l, const float* __restrict__ attn_r)
{
    __shared__ float xs[64][32];
    __shared__ float ws[32][HC];
    int tid = threadIdx.x;
    int tx = tid & 31, ty = tid >> 5;
    int row0 = blockIdx.x * 64;

    float c[8][4];
#pragma unroll
    for (int i = 0; i < 8; i++)
#pragma unroll
        for (int j = 0; j < 4; j++) c[i][j] = 0.f;

    for (int k0 = 0; k0 < IN_F; k0 += 32) {
#pragma unroll
        for (int l = 0; l < 8; l++) {           // x tile: 64x32
            int idx = tid + l * 256;
            int r = idx >> 5, k = idx & 31;
            int row = row0 + r;
            xs[r][k] = (row < NN) ? x[row * IN_F + k0 + k] : 0.f;
        }
#pragma unroll
        for (int l = 0; l < 16; l++) {          // W tile: 32x128
            int idx = tid + l * 256;
            int k = idx >> 7, col = idx & 127;
            ws[k][col] = W[(k0 + k) * HC + col];
        }
        __syncthreads();
#pragma unroll
        for (int k = 0; k < 32; k++) {
            float a[8], b[4];
#pragma unroll
            for (int i = 0; i < 8; i++) a[i] = xs[ty * 8 + i][k];
#pragma unroll
            for (int j = 0; j < 4; j++) b[j] = ws[k][tx * 4 + j];
#pragma unroll
            for (int i = 0; i < 8; i++)
#pragma unroll
                for (int j = 0; j < 4; j++) c[i][j] += a[i] * b[j];
        }
        __syncthreads();
    }

    // attention vectors for this thread's 4 columns (flat [H*C] layout)
    float al[4], ar[4];
#pragma unroll
    for (int j = 0; j < 4; j++) {
        al[j] = attn_l[tx * 4 + j];
        ar[j] = attn_r[tx * 4 + j];
    }
    int head = tx >> 3;   // 8 lanes per head (32 cols / 4 per lane)

#pragma unroll
    for (int i = 0; i < 8; i++) {
        int row = row0 + ty * 8 + i;
        if (row < NN) {
            float4 v = make_float4(c[i][0], c[i][1], c[i][2], c[i][3]);
            *reinterpret_cast<float4*>(&g_feat[(size_t)row * HC + tx * 4]) = v;
        }
        float pl = c[i][0]*al[0] + c[i][1]*al[1] + c[i][2]*al[2] + c[i][3]*al[3];
        float pr = c[i][0]*ar[0] + c[i][1]*ar[1] + c[i][2]*ar[2] + c[i][3]*ar[3];
#pragma unroll
        for (int off = 4; off > 0; off >>= 1) {
            pl += __shfl_down_sync(0xffffffffu, pl, off);
            pr += __shfl_down_sync(0xffffffffu, pr, off);
        }
        if ((tx & 7) == 0 && row < NN) {
            g_el[row * HH + head] = pl;
            g_er[row * HH + head] = pr;
        }
    }
}

// ---------------- kernel 2: zero accumulators ----------------
__global__ void zero_kernel() {
    int i = blockIdx.x * blockDim.x + threadIdx.x;
    float4 z = make_float4(0.f, 0.f, 0.f, 0.f);
    if (i < NN * HC / 4) reinterpret_cast<float4*>(g_acc)[i] = z;
    if (i < NN * HH / 4) reinterpret_cast<float4*>(g_s)[i] = z;
}

// ---------------- kernel 3: per-edge exp + denominator ----------------
// Softmax is shift-invariant; |e| <~ 8 here, so skipping the segment_max pass
// is exact math and safe in fp32.
__global__ void edge_exp_kernel(const int* __restrict__ src,
                                const int* __restrict__ dst)
{
    int e = blockIdx.x * blockDim.x + threadIdx.x;
    if (e >= EE) return;
    int s = src[e], d = dst[e];
    float4 el = reinterpret_cast<const float4*>(g_el)[s];
    float4 er = reinterpret_cast<const float4*>(g_er)[d];
    float v0 = el.x + er.x, v1 = el.y + er.y, v2 = el.z + er.z, v3 = el.w + er.w;
    v0 = v0 > 0.f ? v0 : 0.2f * v0;
    v1 = v1 > 0.f ? v1 : 0.2f * v1;
    v2 = v2 > 0.f ? v2 : 0.2f * v2;
    v3 = v3 > 0.f ? v3 : 0.2f * v3;
    float4 ex = make_float4(expf(v0), expf(v1), expf(v2), expf(v3));
    reinterpret_cast<float4*>(g_ex)[e] = ex;
    atomicAdd(reinterpret_cast<float4*>(g_s) + d, ex);   // vector red, sm_90+
}

// ---------------- kernel 4: warp-per-edge weighted scatter ----------------
__global__ __launch_bounds__(256) void aggregate_kernel(
    const int* __restrict__ src, const int* __restrict__ dst)
{
    int warp = (blockIdx.x * blockDim.x + threadIdx.x) >> 5;
    int lane = threadIdx.x & 31;
    if (warp >= EE) return;
    int s = __ldg(&src[warp]);
    int d = __ldg(&dst[warp]);
    int head = lane >> 3;   // lanes 0-7 head0, 8-15 head1, ...
    float alpha = g_ex[(size_t)warp * HH + head] / g_s[d * HH + head];
    float4 f = reinterpret_cast<const float4*>(g_feat)[(size_t)s * 32 + lane];
    float4 m = make_float4(f.x * alpha, f.y * alpha, f.z * alpha, f.w * alpha);
    atomicAdd(reinterpret_cast<float4*>(g_acc) + (size_t)d * 32 + lane, m);
}

// ---------------- kernel 5: mean over heads + bias + relu ----------------
__global__ void finalize_kernel(const float* __restrict__ bias,
                                float* __restrict__ out)
{
    int i = blockIdx.x * blockDim.x + threadIdx.x;   // n*32 + c
    if (i >= NN * CC) return;
    int n = i >> 5, c = i & 31;
    float acc = 0.f;
#pragma unroll
    for (int h = 0; h < HH; h++)
        acc += g_acc[(size_t)n * HC + h * CC + c] + bias[h * CC + c];
    acc *= 0.25f;
    out[i] = fmaxf(acc, 0.f);
}

// ---------------- launch ----------------
extern "C" void kernel_launch(void* const* d_in, const int* in_sizes, int n_in,
                              void* d_out, int out_size)
{
    const float* x      = (const float*)d_in[0];
    const int*   src    = (const int*)d_in[1];
    const int*   dst    = (const int*)d_in[2];
    const float* W      = (const float*)d_in[3];
    const float* attn_l = (const float*)d_in[4];
    const float* attn_r = (const float*)d_in[5];
    const float* bias   = (const float*)d_in[6];
    float* out = (float*)d_out;

    gemm_feat_kernel<<<(NN + 63) / 64, 256>>>(x, W, attn_l, attn_r);
    zero_kernel<<<(NN * HC / 4 + 255) / 256, 256>>>();
    edge_exp_kernel<<<(EE + 255) / 256, 256>>>(src, dst);
    aggregate_kernel<<<((size_t)EE * 32 + 255) / 256, 256>>>(src, dst);
    finalize_kernel<<<(NN * CC + 255) / 256, 256>>>(bias, out);
}

// round 2
// speedup vs baseline: 1.6523x; 1.6523x over previous
#include <cuda_runtime.h>
#include <cuda_bf16.h>

#define NN 100000
#define EE 1600000
#define IN_F 256
#define HH 4
#define CC 32
#define HC 128           // HH*CC
#define NB 98            // ceil(NN/1024) scan blocks

// ---------------- device scratch (no allocations allowed) ----------------
__device__ float g_feat[NN * HC];     // projected features [N, H*C]
__device__ float g_el[NN * HH];       // left attention logits  [N,H]
__device__ float g_er[NN * HH];       // right attention logits [N,H]
__device__ int   g_deg[NN];           // in-degree histogram
__device__ int   g_rowoff[NN + 1];    // CSR row offsets (by dst)
__device__ int   g_cursor[NN];        // scatter cursors
__device__ int   g_blocksums[128];    // scan partials
__device__ int   g_srcsorted[EE];     // src node id per edge, grouped by dst

// ---------------- kernel 1: feat = x @ W, fused el/er epilogue ----------------
__global__ __launch_bounds__(256) void gemm_feat_kernel(
    const float* __restrict__ x, const float* __restrict__ W,
    const float* __restrict__ attn_l, const float* __restrict__ attn_r)
{
    __shared__ float xs[64][32];
    __shared__ float ws[32][HC];
    int tid = threadIdx.x;
    int tx = tid & 31, ty = tid >> 5;
    int row0 = blockIdx.x * 64;

    float c[8][4];
#pragma unroll
    for (int i = 0; i < 8; i++)
#pragma unroll
        for (int j = 0; j < 4; j++) c[i][j] = 0.f;

    for (int k0 = 0; k0 < IN_F; k0 += 32) {
#pragma unroll
        for (int l = 0; l < 8; l++) {           // x tile: 64x32
            int idx = tid + l * 256;
            int r = idx >> 5, k = idx & 31;
            int row = row0 + r;
            xs[r][k] = (row < NN) ? x[row * IN_F + k0 + k] : 0.f;
        }
#pragma unroll
        for (int l = 0; l < 16; l++) {          // W tile: 32x128
            int idx = tid + l * 256;
            int k = idx >> 7, col = idx & 127;
            ws[k][col] = W[(k0 + k) * HC + col];
        }
        __syncthreads();
#pragma unroll
        for (int k = 0; k < 32; k++) {
            float a[8], b[4];
#pragma unroll
            for (int i = 0; i < 8; i++) a[i] = xs[ty * 8 + i][k];
#pragma unroll
            for (int j = 0; j < 4; j++) b[j] = ws[k][tx * 4 + j];
#pragma unroll
            for (int i = 0; i < 8; i++)
#pragma unroll
                for (int j = 0; j < 4; j++) c[i][j] += a[i] * b[j];
        }
        __syncthreads();
    }

    float al[4], ar[4];
#pragma unroll
    for (int j = 0; j < 4; j++) {
        al[j] = attn_l[tx * 4 + j];
        ar[j] = attn_r[tx * 4 + j];
    }
    int head = tx >> 3;

#pragma unroll
    for (int i = 0; i < 8; i++) {
        int row = row0 + ty * 8 + i;
        if (row < NN) {
            float4 v = make_float4(c[i][0], c[i][1], c[i][2], c[i][3]);
            *reinterpret_cast<float4*>(&g_feat[(size_t)row * HC + tx * 4]) = v;
        }
        float pl = c[i][0]*al[0] + c[i][1]*al[1] + c[i][2]*al[2] + c[i][3]*al[3];
        float pr = c[i][0]*ar[0] + c[i][1]*ar[1] + c[i][2]*ar[2] + c[i][3]*ar[3];
#pragma unroll
        for (int off = 4; off > 0; off >>= 1) {
            pl += __shfl_down_sync(0xffffffffu, pl, off);
            pr += __shfl_down_sync(0xffffffffu, pr, off);
        }
        if ((tx & 7) == 0 && row < NN) {
            g_el[row * HH + head] = pl;
            g_er[row * HH + head] = pr;
        }
    }
}

// ---------------- CSR build ----------------
__global__ void zero_deg_kernel() {
    int i = blockIdx.x * blockDim.x + threadIdx.x;
    if (i < NN) g_deg[i] = 0;
}

__global__ void histo_kernel(const int* __restrict__ dst) {
    int e = blockIdx.x * blockDim.x + threadIdx.x;
    if (e < EE) atomicAdd(&g_deg[dst[e]], 1);
}

__global__ __launch_bounds__(1024) void scan1_kernel() {
    __shared__ int sh[1024];
    int i = blockIdx.x * 1024 + threadIdx.x;
    int v = (i < NN) ? g_deg[i] : 0;
    sh[threadIdx.x] = v;
    __syncthreads();
#pragma unroll
    for (int off = 1; off < 1024; off <<= 1) {
        int t = (threadIdx.x >= off) ? sh[threadIdx.x - off] : 0;
        __syncthreads();
        sh[threadIdx.x] += t;
        __syncthreads();
    }
    if (i < NN) g_rowoff[i] = sh[threadIdx.x] - v;        // exclusive
    if (threadIdx.x == 1023) g_blocksums[blockIdx.x] = sh[1023];
}

__global__ void scan2_kernel() {
    __shared__ int sh[128];
    int v = (threadIdx.x < NB) ? g_blocksums[threadIdx.x] : 0;
    sh[threadIdx.x] = v;
    __syncthreads();
#pragma unroll
    for (int off = 1; off < 128; off <<= 1) {
        int t = (threadIdx.x >= off) ? sh[threadIdx.x - off] : 0;
        __syncthreads();
        sh[threadIdx.x] += t;
        __syncthreads();
    }
    if (threadIdx.x < NB) g_blocksums[threadIdx.x] = sh[threadIdx.x] - v;  // exclusive
}

__global__ __launch_bounds__(1024) void scan3_kernel() {
    int i = blockIdx.x * 1024 + threadIdx.x;
    if (i < NN) {
        int v = g_rowoff[i] + g_blocksums[blockIdx.x];
        g_rowoff[i] = v;
        g_cursor[i] = v;
    }
    if (i == 0) g_rowoff[NN] = EE;
}

__global__ void scatter_kernel(const int* __restrict__ src,
                               const int* __restrict__ dst) {
    int e = blockIdx.x * blockDim.x + threadIdx.x;
    if (e >= EE) return;
    int pos = atomicAdd(&g_cursor[dst[e]], 1);
    g_srcsorted[pos] = src[e];
}

// ---------------- fused softmax + aggregate + head-mean + relu ----------------
// One warp per dst node.
__global__ __launch_bounds__(256) void aggregate_fused_kernel(
    const float* __restrict__ bias, float* __restrict__ out)
{
    int warp = (blockIdx.x * blockDim.x + threadIdx.x) >> 5;
    int lane = threadIdx.x & 31;
    if (warp >= NN) return;
    int n = warp;
    int head = lane >> 3;

    int start = g_rowoff[n];
    int end   = g_rowoff[n + 1];

    float4 er4 = *reinterpret_cast<const float4*>(&g_er[n * HH]);

    // phase 1: softmax denominators per head (lanes parallel over edges)
    float d0 = 0.f, d1 = 0.f, d2 = 0.f, d3 = 0.f;
    for (int j = start + lane; j < end; j += 32) {
        int s = g_srcsorted[j];
        float4 el4 = *reinterpret_cast<const float4*>(&g_el[s * HH]);
        float v0 = el4.x + er4.x, v1 = el4.y + er4.y;
        float v2 = el4.z + er4.z, v3 = el4.w + er4.w;
        v0 = v0 > 0.f ? v0 : 0.2f * v0;
        v1 = v1 > 0.f ? v1 : 0.2f * v1;
        v2 = v2 > 0.f ? v2 : 0.2f * v2;
        v3 = v3 > 0.f ? v3 : 0.2f * v3;
        d0 += __expf(v0); d1 += __expf(v1); d2 += __expf(v2); d3 += __expf(v3);
    }
#pragma unroll
    for (int off = 16; off > 0; off >>= 1) {
        d0 += __shfl_xor_sync(0xffffffffu, d0, off);
        d1 += __shfl_xor_sync(0xffffffffu, d1, off);
        d2 += __shfl_xor_sync(0xffffffffu, d2, off);
        d3 += __shfl_xor_sync(0xffffffffu, d3, off);
    }
    float denom = (head == 0) ? d0 : (head == 1) ? d1 : (head == 2) ? d2 : d3;
    float rinv = __fdividef(1.f, denom);
    float er_mine = (head == 0) ? er4.x : (head == 1) ? er4.y
                   : (head == 2) ? er4.z : er4.w;

    // phase 2: weighted aggregation (warp cooperates per edge)
    float4 acc = make_float4(0.f, 0.f, 0.f, 0.f);
    for (int j = start; j < end; j++) {
        int s = g_srcsorted[j];                     // broadcast load
        float lh = g_el[s * HH + head];
        float v = lh + er_mine;
        v = v > 0.f ? v : 0.2f * v;
        float alpha = __expf(v) * rinv;
        float4 f = reinterpret_cast<const float4*>(g_feat)[(size_t)s * 32 + lane];
        acc.x += alpha * f.x; acc.y += alpha * f.y;
        acc.z += alpha * f.z; acc.w += alpha * f.w;
    }

    // head mean: sum over lane-groups differing in bits 3,4
#pragma unroll
    for (int off = 8; off <= 16; off <<= 1) {
        acc.x += __shfl_xor_sync(0xffffffffu, acc.x, off);
        acc.y += __shfl_xor_sync(0xffffffffu, acc.y, off);
        acc.z += __shfl_xor_sync(0xffffffffu, acc.z, off);
        acc.w += __shfl_xor_sync(0xffffffffu, acc.w, off);
    }
    if (lane < 8) {
        float bs[4] = {0.f, 0.f, 0.f, 0.f};
#pragma unroll
        for (int h = 0; h < HH; h++) {
#pragma unroll
            for (int k = 0; k < 4; k++) bs[k] += bias[h * CC + lane * 4 + k];
        }
        float4 o;
        o.x = fmaxf(0.25f * (acc.x + bs[0]), 0.f);
        o.y = fmaxf(0.25f * (acc.y + bs[1]), 0.f);
        o.z = fmaxf(0.25f * (acc.z + bs[2]), 0.f);
        o.w = fmaxf(0.25f * (acc.w + bs[3]), 0.f);
        reinterpret_cast<float4*>(out)[n * 8 + lane] = o;
    }
}

// ---------------- launch ----------------
extern "C" void kernel_launch(void* const* d_in, const int* in_sizes, int n_in,
                              void* d_out, int out_size)
{
    const float* x      = (const float*)d_in[0];
    const int*   src    = (const int*)d_in[1];
    const int*   dst    = (const int*)d_in[2];
    const float* W      = (const float*)d_in[3];
    const float* attn_l = (const float*)d_in[4];
    const float* attn_r = (const float*)d_in[5];
    const float* bias   = (const float*)d_in[6];
    float* out = (float*)d_out;

    gemm_feat_kernel<<<(NN + 63) / 64, 256>>>(x, W, attn_l, attn_r);

    zero_deg_kernel<<<(NN + 255) / 256, 256>>>();
    histo_kernel<<<(EE + 255) / 256, 256>>>(dst);
    scan1_kernel<<<NB, 1024>>>();
    scan2_kernel<<<1, 128>>>();
    scan3_kernel<<<NB, 1024>>>();
    scatter_kernel<<<(EE + 255) / 256, 256>>>(src, dst);

    aggregate_fused_kernel<<<(NN * 32 + 255) / 256, 256>>>(bias, out);
}

// round 4
// speedup vs baseline: 2.3916x; 1.4474x over previous
#include <cstdint>
#include <cuda_runtime.h>
#include <cuda_bf16.h>

#define NN 100000
#define EE 1600000
#define IN_F 256
#define HH 4
#define CC 32
#define HC 128           // HH*CC
#define NB 98            // ceil(NN/1024) scan blocks
#define AST 40           // smem stride in bf16 (80B rows: conflict-free ldmatrix)

// ---------------- device scratch (no allocations allowed) ----------------
__device__ float g_feat[NN * HC];     // projected features [N, H*C]
__device__ float g_el[NN * HH];       // left attention logits  [N,H]
__device__ float g_er[NN * HH];       // right attention logits [N,H]
__device__ int   g_deg[NN];           // in-degree histogram
__device__ int   g_rowoff[NN + 1];    // CSR row offsets (by dst)
__device__ int   g_cursor[NN];        // scatter cursors
__device__ int   g_blocksums[128];    // scan partials
__device__ int   g_srcsorted[EE];     // src node id per edge, grouped by dst
__device__ __nv_bfloat16 g_Wt_hi[HC * IN_F];  // W^T split hi: [n=128][k=256]
__device__ __nv_bfloat16 g_Wt_lo[HC * IN_F];  // W^T split lo

__device__ __forceinline__ void split_bf16(float v, __nv_bfloat16& h, __nv_bfloat16& l) {
    h = __float2bfloat16(v);
    l = __float2bfloat16(v - __bfloat162float(h));
}

// ---------------- kernel 0: split W into transposed bf16 hi/lo ----------------
__global__ void wprep_kernel(const float* __restrict__ W) {
    int i = blockIdx.x * blockDim.x + threadIdx.x;  // over 256*128
    if (i >= IN_F * HC) return;
    int k = i >> 7, n = i & 127;
    __nv_bfloat16 h, l;
    split_bf16(W[i], h, l);
    g_Wt_hi[n * IN_F + k] = h;
    g_Wt_lo[n * IN_F + k] = l;
}

// ---------------- kernel 1: feat = x @ W via split-bf16 tensor cores ----------
// 3 passes: xh*Wh + xh*Wl + xl*Wh  (drops ~2^-17 lo*lo term).
// Block: 128x128 out tile, 256 thr = 8 warps as 4(m) x 2(n); warp tile 32x64.
// Fused epilogue computes el/er per (row, head) via quad-shfl reduction.
__global__ __launch_bounds__(256) void gemm_feat_tc_kernel(
    const float* __restrict__ x,
    const float* __restrict__ attn_l, const float* __restrict__ attn_r)
{
    __shared__ __nv_bfloat16 Ah[128][AST];
    __shared__ __nv_bfloat16 Al[128][AST];
    __shared__ __nv_bfloat16 Bh[128][AST];
    __shared__ __nv_bfloat16 Bl[128][AST];

    int tid = threadIdx.x, lane = tid & 31, wid = tid >> 5;
    int warp_m = wid >> 1;          // 0..3
    int warp_n = wid & 1;           // 0..1
    int row0 = blockIdx.x * 128;

    float acc[2][8][4];
#pragma unroll
    for (int im = 0; im < 2; im++)
#pragma unroll
        for (int jn = 0; jn < 8; jn++)
#pragma unroll
            for (int r = 0; r < 4; r++) acc[im][jn][r] = 0.f;

    for (int k0 = 0; k0 < IN_F; k0 += 32) {
        // x tile: 128 rows x 32 k, fp32 -> split bf16
#pragma unroll
        for (int l = 0; l < 4; l++) {
            int idx = tid + l * 256;            // 0..1023 float4 slots
            int r = idx >> 3, c4 = (idx & 7) << 2;
            int row = row0 + r;
            float4 v = make_float4(0.f, 0.f, 0.f, 0.f);
            if (row < NN)
                v = *reinterpret_cast<const float4*>(&x[(size_t)row * IN_F + k0 + c4]);
            __nv_bfloat16 h0, l0, h1, l1, h2, l2, h3, l3;
            split_bf16(v.x, h0, l0); split_bf16(v.y, h1, l1);
            split_bf16(v.z, h2, l2); split_bf16(v.w, h3, l3);
            *reinterpret_cast<__nv_bfloat162*>(&Ah[r][c4])     = __nv_bfloat162{h0, h1};
            *reinterpret_cast<__nv_bfloat162*>(&Ah[r][c4 + 2]) = __nv_bfloat162{h2, h3};
            *reinterpret_cast<__nv_bfloat162*>(&Al[r][c4])     = __nv_bfloat162{l0, l1};
            *reinterpret_cast<__nv_bfloat162*>(&Al[r][c4 + 2]) = __nv_bfloat162{l2, l3};
        }
        // W tiles: [128 n][32 k] bf16, preconverted
#pragma unroll
        for (int l = 0; l < 2; l++) {
            int idx8 = tid + l * 256;           // 0..511 uint4 slots
            int n = idx8 >> 2, k8 = (idx8 & 3) << 3;
            *reinterpret_cast<uint4*>(&Bh[n][k8]) =
                *reinterpret_cast<const uint4*>(&g_Wt_hi[n * IN_F + k0 + k8]);
            *reinterpret_cast<uint4*>(&Bl[n][k8]) =
                *reinterpret_cast<const uint4*>(&g_Wt_lo[n * IN_F + k0 + k8]);
        }
        __syncthreads();

#pragma unroll
        for (int kk = 0; kk < 32; kk += 16) {
            uint32_t ah[2][4], al[2][4];
#pragma unroll
            for (int im = 0; im < 2; im++) {
                uint32_t adr_h = (uint32_t)__cvta_generic_to_shared(
                    &Ah[warp_m * 32 + im * 16 + (lane & 15)][kk + ((lane >> 4) << 3)]);
                asm volatile("ldmatrix.sync.aligned.m8n8.x4.shared.b16 {%0,%1,%2,%3}, [%4];"
                             : "=r"(ah[im][0]), "=r"(ah[im][1]), "=r"(ah[im][2]), "=r"(ah[im][3])
                             : "r"(adr_h));
                uint32_t adr_l = (uint32_t)__cvta_generic_to_shared(
                    &Al[warp_m * 32 + im * 16 + (lane & 15)][kk + ((lane >> 4) << 3)]);
                asm volatile("ldmatrix.sync.aligned.m8n8.x4.shared.b16 {%0,%1,%2,%3}, [%4];"
                             : "=r"(al[im][0]), "=r"(al[im][1]), "=r"(al[im][2]), "=r"(al[im][3])
                             : "r"(adr_l));
            }
#pragma unroll
            for (int jn = 0; jn < 8; jn++) {
                int nb = warp_n * 64 + jn * 8;
                uint32_t bh[2], bl[2];
                uint32_t adr_bh = (uint32_t)__cvta_generic_to_shared(
                    &Bh[nb + (lane & 7)][kk + (((lane >> 3) & 1) << 3)]);
                asm volatile("ldmatrix.sync.aligned.m8n8.x2.shared.b16 {%0,%1}, [%2];"
                             : "=r"(bh[0]), "=r"(bh[1]) : "r"(adr_bh));
                uint32_t adr_bl = (uint32_t)__cvta_generic_to_shared(
                    &Bl[nb + (lane & 7)][kk + (((lane >> 3) & 1) << 3)]);
                asm volatile("ldmatrix.sync.aligned.m8n8.x2.shared.b16 {%0,%1}, [%2];"
                             : "=r"(bl[0]), "=r"(bl[1]) : "r"(adr_bl));
#pragma unroll
                for (int im = 0; im < 2; im++) {
                    float* c = acc[im][jn];
                    asm volatile(
                        "mma.sync.aligned.m16n8k16.row.col.f32.bf16.bf16.f32 "
                        "{%0,%1,%2,%3}, {%4,%5,%6,%7}, {%8,%9}, {%0,%1,%2,%3};"
                        : "+f"(c[0]), "+f"(c[1]), "+f"(c[2]), "+f"(c[3])
                        : "r"(ah[im][0]), "r"(ah[im][1]), "r"(ah[im][2]), "r"(ah[im][3]),
                          "r"(bh[0]), "r"(bh[1]));
                    asm volatile(
                        "mma.sync.aligned.m16n8k16.row.col.f32.bf16.bf16.f32 "
                        "{%0,%1,%2,%3}, {%4,%5,%6,%7}, {%8,%9}, {%0,%1,%2,%3};"
                        : "+f"(c[0]), "+f"(c[1]), "+f"(c[2]), "+f"(c[3])
                        : "r"(ah[im][0]), "r"(ah[im][1]), "r"(ah[im][2]), "r"(ah[im][3]),
                          "r"(bl[0]), "r"(bl[1]));
                    asm volatile(
                        "mma.sync.aligned.m16n8k16.row.col.f32.bf16.bf16.f32 "
                        "{%0,%1,%2,%3}, {%4,%5,%6,%7}, {%8,%9}, {%0,%1,%2,%3};"
                        : "+f"(c[0]), "+f"(c[1]), "+f"(c[2]), "+f"(c[3])
                        : "r"(al[im][0]), "r"(al[im][1]), "r"(al[im][2]), "r"(al[im][3]),
                          "r"(bh[0]), "r"(bh[1]));
                }
            }
        }
        __syncthreads();
    }

    // ---- epilogue: store feat, compute el/er per (row, head) ----
    int quad = lane >> 2, tc = lane & 3;
    float pel[2][2][2], per[2][2][2];   // [im][rowhalf][headhalf]
#pragma unroll
    for (int im = 0; im < 2; im++)
#pragma unroll
        for (int rh = 0; rh < 2; rh++)
#pragma unroll
            for (int hh = 0; hh < 2; hh++) { pel[im][rh][hh] = 0.f; per[im][rh][hh] = 0.f; }

#pragma unroll
    for (int im = 0; im < 2; im++) {
        int rowA = row0 + warp_m * 32 + im * 16 + quad;
#pragma unroll
        for (int jn = 0; jn < 8; jn++) {
            int col = warp_n * 64 + jn * 8 + tc * 2;
            int hh = jn >> 2;
            float* c = acc[im][jn];
            float a0 = attn_l[col], a1 = attn_l[col + 1];
            float b0 = attn_r[col], b1 = attn_r[col + 1];
            pel[im][0][hh] += c[0] * a0 + c[1] * a1;
            per[im][0][hh] += c[0] * b0 + c[1] * b1;
            pel[im][1][hh] += c[2] * a0 + c[3] * a1;
            per[im][1][hh] += c[2] * b0 + c[3] * b1;
            if (rowA < NN)
                *reinterpret_cast<float2*>(&g_feat[(size_t)rowA * HC + col]) =
                    make_float2(c[0], c[1]);
            if (rowA + 8 < NN)
                *reinterpret_cast<float2*>(&g_feat[(size_t)(rowA + 8) * HC + col]) =
                    make_float2(c[2], c[3]);
        }
    }
#pragma unroll
    for (int im = 0; im < 2; im++)
#pragma unroll
        for (int rh = 0; rh < 2; rh++)
#pragma unroll
            for (int hh = 0; hh < 2; hh++) {
                float e = pel[im][rh][hh], r = per[im][rh][hh];
                e += __shfl_xor_sync(0xffffffffu, e, 1);
                e += __shfl_xor_sync(0xffffffffu, e, 2);
                r += __shfl_xor_sync(0xffffffffu, r, 1);
                r += __shfl_xor_sync(0xffffffffu, r, 2);
                if (tc == 0) {
                    int row = row0 + warp_m * 32 + im * 16 + quad + rh * 8;
                    int head = warp_n * 2 + hh;
                    if (row < NN) {
                        g_el[row * HH + head] = e;
                        g_er[row * HH + head] = r;
                    }
                }
            }
}

// ---------------- CSR build ----------------
__global__ void zero_deg_kernel() {
    int i = blockIdx.x * blockDim.x + threadIdx.x;
    if (i < NN) g_deg[i] = 0;
}

__global__ void histo_kernel(const int* __restrict__ dst) {
    int e = blockIdx.x * blockDim.x + threadIdx.x;
    if (e < EE) atomicAdd(&g_deg[dst[e]], 1);
}

__global__ __launch_bounds__(1024) void scan1_kernel() {
    __shared__ int sh[1024];
    int i = blockIdx.x * 1024 + threadIdx.x;
    int v = (i < NN) ? g_deg[i] : 0;
    sh[threadIdx.x] = v;
    __syncthreads();
#pragma unroll
    for (int off = 1; off < 1024; off <<= 1) {
        int t = (threadIdx.x >= off) ? sh[threadIdx.x - off] : 0;
        __syncthreads();
        sh[threadIdx.x] += t;
        __syncthreads();
    }
    if (i < NN) g_rowoff[i] = sh[threadIdx.x] - v;        // exclusive
    if (threadIdx.x == 1023) g_blocksums[blockIdx.x] = sh[1023];
}

__global__ void scan2_kernel() {
    __shared__ int sh[128];
    int v = (threadIdx.x < NB) ? g_blocksums[threadIdx.x] : 0;
    sh[threadIdx.x] = v;
    __syncthreads();
#pragma unroll
    for (int off = 1; off < 128; off <<= 1) {
        int t = (threadIdx.x >= off) ? sh[threadIdx.x - off] : 0;
        __syncthreads();
        sh[threadIdx.x] += t;
        __syncthreads();
    }
    if (threadIdx.x < NB) g_blocksums[threadIdx.x] = sh[threadIdx.x] - v;  // exclusive
}

__global__ __launch_bounds__(1024) void scan3_kernel() {
    int i = blockIdx.x * 1024 + threadIdx.x;
    if (i < NN) {
        int v = g_rowoff[i] + g_blocksums[blockIdx.x];
        g_rowoff[i] = v;
        g_cursor[i] = v;
    }
    if (i == 0) g_rowoff[NN] = EE;
}

__global__ void scatter_kernel(const int* __restrict__ src,
                               const int* __restrict__ dst) {
    int e = blockIdx.x * blockDim.x + threadIdx.x;
    if (e >= EE) return;
    int pos = atomicAdd(&g_cursor[dst[e]], 1);
    g_srcsorted[pos] = src[e];
}

// ---------------- fused softmax + aggregate + head-mean + relu ----------------
__global__ __launch_bounds__(256) void aggregate_fused_kernel(
    const float* __restrict__ bias, float* __restrict__ out)
{
    int warp = (blockIdx.x * blockDim.x + threadIdx.x) >> 5;
    int lane = threadIdx.x & 31;
    if (warp >= NN) return;
    int n = warp;
    int head = lane >> 3;

    int start = g_rowoff[n];
    int end   = g_rowoff[n + 1];

    float4 er4 = *reinterpret_cast<const float4*>(&g_er[n * HH]);

    float d0 = 0.f, d1 = 0.f, d2 = 0.f, d3 = 0.f;
    for (int j = start + lane; j < end; j += 32) {
        int s = g_srcsorted[j];
        float4 el4 = *reinterpret_cast<const float4*>(&g_el[s * HH]);
        float v0 = el4.x + er4.x, v1 = el4.y + er4.y;
        float v2 = el4.z + er4.z, v3 = el4.w + er4.w;
        v0 = v0 > 0.f ? v0 : 0.2f * v0;
        v1 = v1 > 0.f ? v1 : 0.2f * v1;
        v2 = v2 > 0.f ? v2 : 0.2f * v2;
        v3 = v3 > 0.f ? v3 : 0.2f * v3;
        d0 += __expf(v0); d1 += __expf(v1); d2 += __expf(v2); d3 += __expf(v3);
    }
#pragma unroll
    for (int off = 16; off > 0; off >>= 1) {
        d0 += __shfl_xor_sync(0xffffffffu, d0, off);
        d1 += __shfl_xor_sync(0xffffffffu, d1, off);
        d2 += __shfl_xor_sync(0xffffffffu, d2, off);
        d3 += __shfl_xor_sync(0xffffffffu, d3, off);
    }
    float denom = (head == 0) ? d0 : (head == 1) ? d1 : (head == 2) ? d2 : d3;
    float rinv = __fdividef(1.f, denom);
    float er_mine = (head == 0) ? er4.x : (head == 1) ? er4.y
                   : (head == 2) ? er4.z : er4.w;

    float4 acc = make_float4(0.f, 0.f, 0.f, 0.f);
    for (int j = start; j < end; j++) {
        int s = g_srcsorted[j];                     // broadcast load
        float lh = g_el[s * HH + head];
        float v = lh + er_mine;
        v = v > 0.f ? v : 0.2f * v;
        float alpha = __expf(v) * rinv;
        float4 f = reinterpret_cast<const float4*>(g_feat)[(size_t)s * 32 + lane];
        acc.x += alpha * f.x; acc.y += alpha * f.y;
        acc.z += alpha * f.z; acc.w += alpha * f.w;
    }

#pragma unroll
    for (int off = 8; off <= 16; off <<= 1) {
        acc.x += __shfl_xor_sync(0xffffffffu, acc.x, off);
        acc.y += __shfl_xor_sync(0xffffffffu, acc.y, off);
        acc.z += __shfl_xor_sync(0xffffffffu, acc.z, off);
        acc.w += __shfl_xor_sync(0xffffffffu, acc.w, off);
    }
    if (lane < 8) {
        float bs[4] = {0.f, 0.f, 0.f, 0.f};
#pragma unroll
        for (int h = 0; h < HH; h++) {
#pragma unroll
            for (int k = 0; k < 4; k++) bs[k] += bias[h * CC + lane * 4 + k];
        }
        float4 o;
        o.x = fmaxf(0.25f * (acc.x + bs[0]), 0.f);
        o.y = fmaxf(0.25f * (acc.y + bs[1]), 0.f);
        o.z = fmaxf(0.25f * (acc.z + bs[2]), 0.f);
        o.w = fmaxf(0.25f * (acc.w + bs[3]), 0.f);
        reinterpret_cast<float4*>(out)[n * 8 + lane] = o;
    }
}

// ---------------- launch ----------------
extern "C" void kernel_launch(void* const* d_in, const int* in_sizes, int n_in,
                              void* d_out, int out_size)
{
    const float* x      = (const float*)d_in[0];
    const int*   src    = (const int*)d_in[1];
    const int*   dst    = (const int*)d_in[2];
    const float* W      = (const float*)d_in[3];
    const float* attn_l = (const float*)d_in[4];
    const float* attn_r = (const float*)d_in[5];
    const float* bias   = (const float*)d_in[6];
    float* out = (float*)d_out;

    wprep_kernel<<<(IN_F * HC + 255) / 256, 256>>>(W);
    gemm_feat_tc_kernel<<<(NN + 127) / 128, 256>>>(x, attn_l, attn_r);

    zero_deg_kernel<<<(NN + 255) / 256, 256>>>();
    histo_kernel<<<(EE + 255) / 256, 256>>>(dst);
    scan1_kernel<<<NB, 1024>>>();
    scan2_kernel<<<1, 128>>>();
    scan3_kernel<<<NB, 1024>>>();
    scatter_kernel<<<(EE + 255) / 256, 256>>>(src, dst);

    aggregate_fused_kernel<<<(NN * 32 + 255) / 256, 256>>>(bias, out);
}

// round 5
// speedup vs baseline: 2.5947x; 1.0849x over previous
#include <cstdint>
#include <cuda_runtime.h>
#include <cuda_fp16.h>
#include <cuda_bf16.h>

#define NN 100000
#define EE 1600000
#define IN_F 256
#define HH 4
#define CC 32
#define HC 128           // HH*CC
#define NB 98            // ceil(NN/1024) scan blocks
#define AST 40           // smem stride in bf16 (80B rows: conflict-free ldmatrix)

// ---------------- device scratch (no allocations allowed) ----------------
__device__ __half g_feat_h[NN * HC];  // projected features [N, H*C] (fp16)
__device__ float g_el[NN * HH];       // left attention logits  [N,H]
__device__ float g_er[NN * HH];       // right attention logits [N,H]
__device__ int   g_deg[NN];           // in-degree histogram
__device__ int   g_rowoff[NN + 1];    // CSR row offsets (by dst)
__device__ int   g_cursor[NN];        // scatter cursors
__device__ int   g_blocksums[128];    // scan partials
__device__ int   g_srcsorted[EE];     // src node id per edge, grouped by dst
__device__ __nv_bfloat16 g_Wt_hi[HC * IN_F];  // W^T split hi: [n=128][k=256]
__device__ __nv_bfloat16 g_Wt_lo[HC * IN_F];  // W^T split lo

__device__ __forceinline__ void split_bf16(float v, __nv_bfloat16& h, __nv_bfloat16& l) {
    h = __float2bfloat16(v);
    l = __float2bfloat16(v - __bfloat162float(h));
}

// ---------------- kernel 0: split W into transposed bf16 hi/lo ----------------
__global__ void wprep_kernel(const float* __restrict__ W) {
    int i = blockIdx.x * blockDim.x + threadIdx.x;  // over 256*128
    if (i >= IN_F * HC) return;
    int k = i >> 7, n = i & 127;
    __nv_bfloat16 h, l;
    split_bf16(W[i], h, l);
    g_Wt_hi[n * IN_F + k] = h;
    g_Wt_lo[n * IN_F + k] = l;
}

// ---------------- kernel 1: feat = x @ W via split-bf16 tensor cores ----------
__global__ __launch_bounds__(256) void gemm_feat_tc_kernel(
    const float* __restrict__ x,
    const float* __restrict__ attn_l, const float* __restrict__ attn_r)
{
    __shared__ __nv_bfloat16 Ah[128][AST];
    __shared__ __nv_bfloat16 Al[128][AST];
    __shared__ __nv_bfloat16 Bh[128][AST];
    __shared__ __nv_bfloat16 Bl[128][AST];

    int tid = threadIdx.x, lane = tid & 31, wid = tid >> 5;
    int warp_m = wid >> 1;          // 0..3
    int warp_n = wid & 1;           // 0..1
    int row0 = blockIdx.x * 128;

    float acc[2][8][4];
#pragma unroll
    for (int im = 0; im < 2; im++)
#pragma unroll
        for (int jn = 0; jn < 8; jn++)
#pragma unroll
            for (int r = 0; r < 4; r++) acc[im][jn][r] = 0.f;

    for (int k0 = 0; k0 < IN_F; k0 += 32) {
#pragma unroll
        for (int l = 0; l < 4; l++) {
            int idx = tid + l * 256;            // 0..1023 float4 slots
            int r = idx >> 3, c4 = (idx & 7) << 2;
            int row = row0 + r;
            float4 v = make_float4(0.f, 0.f, 0.f, 0.f);
            if (row < NN)
                v = *reinterpret_cast<const float4*>(&x[(size_t)row * IN_F + k0 + c4]);
            __nv_bfloat16 h0, l0, h1, l1, h2, l2, h3, l3;
            split_bf16(v.x, h0, l0); split_bf16(v.y, h1, l1);
            split_bf16(v.z, h2, l2); split_bf16(v.w, h3, l3);
            *reinterpret_cast<__nv_bfloat162*>(&Ah[r][c4])     = __nv_bfloat162{h0, h1};
            *reinterpret_cast<__nv_bfloat162*>(&Ah[r][c4 + 2]) = __nv_bfloat162{h2, h3};
            *reinterpret_cast<__nv_bfloat162*>(&Al[r][c4])     = __nv_bfloat162{l0, l1};
            *reinterpret_cast<__nv_bfloat162*>(&Al[r][c4 + 2]) = __nv_bfloat162{l2, l3};
        }
#pragma unroll
        for (int l = 0; l < 2; l++) {
            int idx8 = tid + l * 256;           // 0..511 uint4 slots
            int n = idx8 >> 2, k8 = (idx8 & 3) << 3;
            *reinterpret_cast<uint4*>(&Bh[n][k8]) =
                *reinterpret_cast<const uint4*>(&g_Wt_hi[n * IN_F + k0 + k8]);
            *reinterpret_cast<uint4*>(&Bl[n][k8]) =
                *reinterpret_cast<const uint4*>(&g_Wt_lo[n * IN_F + k0 + k8]);
        }
        __syncthreads();

#pragma unroll
        for (int kk = 0; kk < 32; kk += 16) {
            uint32_t ah[2][4], al[2][4];
#pragma unroll
            for (int im = 0; im < 2; im++) {
                uint32_t adr_h = (uint32_t)__cvta_generic_to_shared(
                    &Ah[warp_m * 32 + im * 16 + (lane & 15)][kk + ((lane >> 4) << 3)]);
                asm volatile("ldmatrix.sync.aligned.m8n8.x4.shared.b16 {%0,%1,%2,%3}, [%4];"
                             : "=r"(ah[im][0]), "=r"(ah[im][1]), "=r"(ah[im][2]), "=r"(ah[im][3])
                             : "r"(adr_h));
                uint32_t adr_l = (uint32_t)__cvta_generic_to_shared(
                    &Al[warp_m * 32 + im * 16 + (lane & 15)][kk + ((lane >> 4) << 3)]);
                asm volatile("ldmatrix.sync.aligned.m8n8.x4.shared.b16 {%0,%1,%2,%3}, [%4];"
                             : "=r"(al[im][0]), "=r"(al[im][1]), "=r"(al[im][2]), "=r"(al[im][3])
                             : "r"(adr_l));
            }
#pragma unroll
            for (int jn = 0; jn < 8; jn++) {
                int nb = warp_n * 64 + jn * 8;
                uint32_t bh[2], bl[2];
                uint32_t adr_bh = (uint32_t)__cvta_generic_to_shared(
                    &Bh[nb + (lane & 7)][kk + (((lane >> 3) & 1) << 3)]);
                asm volatile("ldmatrix.sync.aligned.m8n8.x2.shared.b16 {%0,%1}, [%2];"
                             : "=r"(bh[0]), "=r"(bh[1]) : "r"(adr_bh));
                uint32_t adr_bl = (uint32_t)__cvta_generic_to_shared(
                    &Bl[nb + (lane & 7)][kk + (((lane >> 3) & 1) << 3)]);
                asm volatile("ldmatrix.sync.aligned.m8n8.x2.shared.b16 {%0,%1}, [%2];"
                             : "=r"(bl[0]), "=r"(bl[1]) : "r"(adr_bl));
#pragma unroll
                for (int im = 0; im < 2; im++) {
                    float* c = acc[im][jn];
                    asm volatile(
                        "mma.sync.aligned.m16n8k16.row.col.f32.bf16.bf16.f32 "
                        "{%0,%1,%2,%3}, {%4,%5,%6,%7}, {%8,%9}, {%0,%1,%2,%3};"
                        : "+f"(c[0]), "+f"(c[1]), "+f"(c[2]), "+f"(c[3])
                        : "r"(ah[im][0]), "r"(ah[im][1]), "r"(ah[im][2]), "r"(ah[im][3]),
                          "r"(bh[0]), "r"(bh[1]));
                    asm volatile(
                        "mma.sync.aligned.m16n8k16.row.col.f32.bf16.bf16.f32 "
                        "{%0,%1,%2,%3}, {%4,%5,%6,%7}, {%8,%9}, {%0,%1,%2,%3};"
                        : "+f"(c[0]), "+f"(c[1]), "+f"(c[2]), "+f"(c[3])
                        : "r"(ah[im][0]), "r"(ah[im][1]), "r"(ah[im][2]), "r"(ah[im][3]),
                          "r"(bl[0]), "r"(bl[1]));
                    asm volatile(
                        "mma.sync.aligned.m16n8k16.row.col.f32.bf16.bf16.f32 "
                        "{%0,%1,%2,%3}, {%4,%5,%6,%7}, {%8,%9}, {%0,%1,%2,%3};"
                        : "+f"(c[0]), "+f"(c[1]), "+f"(c[2]), "+f"(c[3])
                        : "r"(al[im][0]), "r"(al[im][1]), "r"(al[im][2]), "r"(al[im][3]),
                          "r"(bh[0]), "r"(bh[1]));
                }
            }
        }
        __syncthreads();
    }

    // ---- epilogue: store feat (fp16), compute el/er per (row, head) ----
    int quad = lane >> 2, tc = lane & 3;
    float pel[2][2][2], per[2][2][2];   // [im][rowhalf][headhalf]
#pragma unroll
    for (int im = 0; im < 2; im++)
#pragma unroll
        for (int rh = 0; rh < 2; rh++)
#pragma unroll
            for (int hh = 0; hh < 2; hh++) { pel[im][rh][hh] = 0.f; per[im][rh][hh] = 0.f; }

#pragma unroll
    for (int im = 0; im < 2; im++) {
        int rowA = row0 + warp_m * 32 + im * 16 + quad;
#pragma unroll
        for (int jn = 0; jn < 8; jn++) {
            int col = warp_n * 64 + jn * 8 + tc * 2;
            int hh = jn >> 2;
            float* c = acc[im][jn];
            float a0 = attn_l[col], a1 = attn_l[col + 1];
            float b0 = attn_r[col], b1 = attn_r[col + 1];
            pel[im][0][hh] += c[0] * a0 + c[1] * a1;
            per[im][0][hh] += c[0] * b0 + c[1] * b1;
            pel[im][1][hh] += c[2] * a0 + c[3] * a1;
            per[im][1][hh] += c[2] * b0 + c[3] * b1;
            if (rowA < NN)
                *reinterpret_cast<__half2*>(&g_feat_h[(size_t)rowA * HC + col]) =
                    __floats2half2_rn(c[0], c[1]);
            if (rowA + 8 < NN)
                *reinterpret_cast<__half2*>(&g_feat_h[(size_t)(rowA + 8) * HC + col]) =
                    __floats2half2_rn(c[2], c[3]);
        }
    }
#pragma unroll
    for (int im = 0; im < 2; im++)
#pragma unroll
        for (int rh = 0; rh < 2; rh++)
#pragma unroll
            for (int hh = 0; hh < 2; hh++) {
                float e = pel[im][rh][hh], r = per[im][rh][hh];
                e += __shfl_xor_sync(0xffffffffu, e, 1);
                e += __shfl_xor_sync(0xffffffffu, e, 2);
                r += __shfl_xor_sync(0xffffffffu, r, 1);
                r += __shfl_xor_sync(0xffffffffu, r, 2);
                if (tc == 0) {
                    int row = row0 + warp_m * 32 + im * 16 + quad + rh * 8;
                    int head = warp_n * 2 + hh;
                    if (row < NN) {
                        g_el[row * HH + head] = e;
                        g_er[row * HH + head] = r;
                    }
                }
            }
}

// ---------------- CSR build ----------------
__global__ void zero_deg_kernel() {
    int i = blockIdx.x * blockDim.x + threadIdx.x;
    if (i < NN) g_deg[i] = 0;
}

__global__ void histo_kernel(const int* __restrict__ dst) {
    int e = blockIdx.x * blockDim.x + threadIdx.x;
    if (e < EE) atomicAdd(&g_deg[dst[e]], 1);
}

__global__ __launch_bounds__(1024) void scan1_kernel() {
    __shared__ int sh[1024];
    int i = blockIdx.x * 1024 + threadIdx.x;
    int v = (i < NN) ? g_deg[i] : 0;
    sh[threadIdx.x] = v;
    __syncthreads();
#pragma unroll
    for (int off = 1; off < 1024; off <<= 1) {
        int t = (threadIdx.x >= off) ? sh[threadIdx.x - off] : 0;
        __syncthreads();
        sh[threadIdx.x] += t;
        __syncthreads();
    }
    if (i < NN) g_rowoff[i] = sh[threadIdx.x] - v;        // exclusive
    if (threadIdx.x == 1023) g_blocksums[blockIdx.x] = sh[1023];
}

__global__ void scan2_kernel() {
    __shared__ int sh[128];
    int v = (threadIdx.x < NB) ? g_blocksums[threadIdx.x] : 0;
    sh[threadIdx.x] = v;
    __syncthreads();
#pragma unroll
    for (int off = 1; off < 128; off <<= 1) {
        int t = (threadIdx.x >= off) ? sh[threadIdx.x - off] : 0;
        __syncthreads();
        sh[threadIdx.x] += t;
        __syncthreads();
    }
    if (threadIdx.x < NB) g_blocksums[threadIdx.x] = sh[threadIdx.x] - v;  // exclusive
}

__global__ __launch_bounds__(1024) void scan3_kernel() {
    int i = blockIdx.x * 1024 + threadIdx.x;
    if (i < NN) {
        int v = g_rowoff[i] + g_blocksums[blockIdx.x];
        g_rowoff[i] = v;
        g_cursor[i] = v;
    }
    if (i == 0) g_rowoff[NN] = EE;
}

__global__ void scatter_kernel(const int* __restrict__ src,
                               const int* __restrict__ dst) {
    int e = blockIdx.x * blockDim.x + threadIdx.x;
    if (e >= EE) return;
    int pos = atomicAdd(&g_cursor[dst[e]], 1);
    g_srcsorted[pos] = src[e];
}

// ---------------- fused softmax + aggregate + head-mean + relu ----------------
__global__ __launch_bounds__(256) void aggregate_fused_kernel(
    const float* __restrict__ bias, float* __restrict__ out)
{
    int warp = (blockIdx.x * blockDim.x + threadIdx.x) >> 5;
    int lane = threadIdx.x & 31;
    if (warp >= NN) return;
    int n = warp;
    int head = lane >> 3;

    int start = g_rowoff[n];
    int end   = g_rowoff[n + 1];

    float4 er4 = *reinterpret_cast<const float4*>(&g_er[n * HH]);

    float d0 = 0.f, d1 = 0.f, d2 = 0.f, d3 = 0.f;
    for (int j = start + lane; j < end; j += 32) {
        int s = g_srcsorted[j];
        float4 el4 = *reinterpret_cast<const float4*>(&g_el[s * HH]);
        float v0 = el4.x + er4.x, v1 = el4.y + er4.y;
        float v2 = el4.z + er4.z, v3 = el4.w + er4.w;
        v0 = v0 > 0.f ? v0 : 0.2f * v0;
        v1 = v1 > 0.f ? v1 : 0.2f * v1;
        v2 = v2 > 0.f ? v2 : 0.2f * v2;
        v3 = v3 > 0.f ? v3 : 0.2f * v3;
        d0 += __expf(v0); d1 += __expf(v1); d2 += __expf(v2); d3 += __expf(v3);
    }
#pragma unroll
    for (int off = 16; off > 0; off >>= 1) {
        d0 += __shfl_xor_sync(0xffffffffu, d0, off);
        d1 += __shfl_xor_sync(0xffffffffu, d1, off);
        d2 += __shfl_xor_sync(0xffffffffu, d2, off);
        d3 += __shfl_xor_sync(0xffffffffu, d3, off);
    }
    float denom = (head == 0) ? d0 : (head == 1) ? d1 : (head == 2) ? d2 : d3;
    float rinv = __fdividef(1.f, denom);
    float er_mine = (head == 0) ? er4.x : (head == 1) ? er4.y
                   : (head == 2) ? er4.z : er4.w;

    // phase 2: fp16 feat gather (256B per edge row)
    float4 acc = make_float4(0.f, 0.f, 0.f, 0.f);
    const uint2* feat2 = reinterpret_cast<const uint2*>(g_feat_h);
    for (int j = start; j < end; j++) {
        int s = g_srcsorted[j];                     // broadcast load
        float lh = g_el[s * HH + head];
        float v = lh + er_mine;
        v = v > 0.f ? v : 0.2f * v;
        float alpha = __expf(v) * rinv;
        uint2 u = feat2[(size_t)s * 32 + lane];     // 4 halves = lane's channels
        float2 f01 = __half22float2(*reinterpret_cast<__half2*>(&u.x));
        float2 f23 = __half22float2(*reinterpret_cast<__half2*>(&u.y));
        acc.x += alpha * f01.x; acc.y += alpha * f01.y;
        acc.z += alpha * f23.x; acc.w += alpha * f23.y;
    }

#pragma unroll
    for (int off = 8; off <= 16; off <<= 1) {
        acc.x += __shfl_xor_sync(0xffffffffu, acc.x, off);
        acc.y += __shfl_xor_sync(0xffffffffu, acc.y, off);
        acc.z += __shfl_xor_sync(0xffffffffu, acc.z, off);
        acc.w += __shfl_xor_sync(0xffffffffu, acc.w, off);
    }
    if (lane < 8) {
        float bs[4] = {0.f, 0.f, 0.f, 0.f};
#pragma unroll
        for (int h = 0; h < HH; h++) {
#pragma unroll
            for (int k = 0; k < 4; k++) bs[k] += bias[h * CC + lane * 4 + k];
        }
        float4 o;
        o.x = fmaxf(0.25f * (acc.x + bs[0]), 0.f);
        o.y = fmaxf(0.25f * (acc.y + bs[1]), 0.f);
        o.z = fmaxf(0.25f * (acc.z + bs[2]), 0.f);
        o.w = fmaxf(0.25f * (acc.w + bs[3]), 0.f);
        reinterpret_cast<float4*>(out)[n * 8 + lane] = o;
    }
}

// ---------------- launch: CSR build forked onto side stream ----------------
extern "C" void kernel_launch(void* const* d_in, const int* in_sizes, int n_in,
                              void* d_out, int out_size)
{
    const float* x      = (const float*)d_in[0];
    const int*   src    = (const int*)d_in[1];
    const int*   dst    = (const int*)d_in[2];
    const float* W      = (const float*)d_in[3];
    const float* attn_l = (const float*)d_in[4];
    const float* attn_r = (const float*)d_in[5];
    const float* bias   = (const float*)d_in[6];
    float* out = (float*)d_out;

    // one-time host resources (created on the pre-capture correctness call)
    static cudaStream_t s2 = nullptr;
    static cudaEvent_t evFork = nullptr, evJoin = nullptr;
    static bool ok2 = false;
    if (!evFork) {
        ok2 = (cudaStreamCreateWithFlags(&s2, cudaStreamNonBlocking) == cudaSuccess);
        cudaEventCreateWithFlags(&evFork, cudaEventDisableTiming);
        cudaEventCreateWithFlags(&evJoin, cudaEventDisableTiming);
    }
    cudaStream_t sb = ok2 ? s2 : (cudaStream_t)0;

    if (ok2) {
        cudaEventRecord(evFork, 0);
        cudaStreamWaitEvent(s2, evFork, 0);
    }

    // CSR chain (side stream)
    zero_deg_kernel<<<(NN + 255) / 256, 256, 0, sb>>>();
    histo_kernel<<<(EE + 255) / 256, 256, 0, sb>>>(dst);
    scan1_kernel<<<NB, 1024, 0, sb>>>();
    scan2_kernel<<<1, 128, 0, sb>>>();
    scan3_kernel<<<NB, 1024, 0, sb>>>();
    scatter_kernel<<<(EE + 255) / 256, 256, 0, sb>>>(src, dst);

    // GEMM chain (main stream)
    wprep_kernel<<<(IN_F * HC + 255) / 256, 256>>>(W);
    gemm_feat_tc_kernel<<<(NN + 127) / 128, 256>>>(x, attn_l, attn_r);

    if (ok2) {
        cudaEventRecord(evJoin, s2);
        cudaStreamWaitEvent(0, evJoin, 0);
    }

    aggregate_fused_kernel<<<(NN * 32 + 255) / 256, 256>>>(bias, out);
}

// round 6
// speedup vs baseline: 2.6579x; 1.0243x over previous
#include <cstdint>
#include <cuda_runtime.h>
#include <cuda_fp16.h>
#include <cuda_bf16.h>

#define NN 100000
#define EE 1600000
#define IN_F 256
#define HH 4
#define CC 32
#define HC 128           // HH*CC
#define NB 98            // ceil(NN/1024) scan blocks
#define AST 40           // smem stride in bf16 (80B rows: conflict-free ldmatrix)

// ---------------- device scratch (no allocations allowed) ----------------
__device__ __half g_feat_h[NN * HC];  // projected features [N, H*C] (fp16)
__device__ float g_el[NN * HH];       // left attention logits  [N,H]
__device__ float g_er[NN * HH];       // right attention logits [N,H]
__device__ int   g_deg[NN];           // in-degree histogram
__device__ int   g_rowoff[NN + 1];    // CSR row offsets (by dst)
__device__ int   g_cursor[NN];        // scatter cursors
__device__ int   g_blocksums[128];    // scan partials
__device__ int   g_srcsorted[EE];     // src node id per edge, grouped by dst
__device__ __nv_bfloat16 g_Wt_hi[HC * IN_F];  // W^T split hi: [n=128][k=256]
__device__ __nv_bfloat16 g_Wt_lo[HC * IN_F];  // W^T split lo

__device__ __forceinline__ void split_bf16(float v, __nv_bfloat16& h, __nv_bfloat16& l) {
    h = __float2bfloat16(v);
    l = __float2bfloat16(v - __bfloat162float(h));
}

// ---------------- kernel 0: split W into transposed bf16 hi/lo ----------------
__global__ void wprep_kernel(const float* __restrict__ W) {
    int i = blockIdx.x * blockDim.x + threadIdx.x;  // over 256*128
    if (i >= IN_F * HC) return;
    int k = i >> 7, n = i & 127;
    __nv_bfloat16 h, l;
    split_bf16(W[i], h, l);
    g_Wt_hi[n * IN_F + k] = h;
    g_Wt_lo[n * IN_F + k] = l;
}

// ---------------- kernel 1: feat = x @ W via split-bf16 tensor cores ----------
__global__ __launch_bounds__(256) void gemm_feat_tc_kernel(
    const float* __restrict__ x,
    const float* __restrict__ attn_l, const float* __restrict__ attn_r)
{
    __shared__ __nv_bfloat16 Ah[128][AST];
    __shared__ __nv_bfloat16 Al[128][AST];
    __shared__ __nv_bfloat16 Bh[128][AST];
    __shared__ __nv_bfloat16 Bl[128][AST];

    int tid = threadIdx.x, lane = tid & 31, wid = tid >> 5;
    int warp_m = wid >> 1;          // 0..3
    int warp_n = wid & 1;           // 0..1
    int row0 = blockIdx.x * 128;

    float acc[2][8][4];
#pragma unroll
    for (int im = 0; im < 2; im++)
#pragma unroll
        for (int jn = 0; jn < 8; jn++)
#pragma unroll
            for (int r = 0; r < 4; r++) acc[im][jn][r] = 0.f;

    for (int k0 = 0; k0 < IN_F; k0 += 32) {
#pragma unroll
        for (int l = 0; l < 4; l++) {
            int idx = tid + l * 256;            // 0..1023 float4 slots
            int r = idx >> 3, c4 = (idx & 7) << 2;
            int row = row0 + r;
            float4 v = make_float4(0.f, 0.f, 0.f, 0.f);
            if (row < NN)
                v = *reinterpret_cast<const float4*>(&x[(size_t)row * IN_F + k0 + c4]);
            __nv_bfloat16 h0, l0, h1, l1, h2, l2, h3, l3;
            split_bf16(v.x, h0, l0); split_bf16(v.y, h1, l1);
            split_bf16(v.z, h2, l2); split_bf16(v.w, h3, l3);
            *reinterpret_cast<__nv_bfloat162*>(&Ah[r][c4])     = __nv_bfloat162{h0, h1};
            *reinterpret_cast<__nv_bfloat162*>(&Ah[r][c4 + 2]) = __nv_bfloat162{h2, h3};
            *reinterpret_cast<__nv_bfloat162*>(&Al[r][c4])     = __nv_bfloat162{l0, l1};
            *reinterpret_cast<__nv_bfloat162*>(&Al[r][c4 + 2]) = __nv_bfloat162{l2, l3};
        }
#pragma unroll
        for (int l = 0; l < 2; l++) {
            int idx8 = tid + l * 256;           // 0..511 uint4 slots
            int n = idx8 >> 2, k8 = (idx8 & 3) << 3;
            *reinterpret_cast<uint4*>(&Bh[n][k8]) =
                *reinterpret_cast<const uint4*>(&g_Wt_hi[n * IN_F + k0 + k8]);
            *reinterpret_cast<uint4*>(&Bl[n][k8]) =
                *reinterpret_cast<const uint4*>(&g_Wt_lo[n * IN_F + k0 + k8]);
        }
        __syncthreads();

#pragma unroll
        for (int kk = 0; kk < 32; kk += 16) {
            uint32_t ah[2][4], al[2][4];
#pragma unroll
            for (int im = 0; im < 2; im++) {
                uint32_t adr_h = (uint32_t)__cvta_generic_to_shared(
                    &Ah[warp_m * 32 + im * 16 + (lane & 15)][kk + ((lane >> 4) << 3)]);
                asm volatile("ldmatrix.sync.aligned.m8n8.x4.shared.b16 {%0,%1,%2,%3}, [%4];"
                             : "=r"(ah[im][0]), "=r"(ah[im][1]), "=r"(ah[im][2]), "=r"(ah[im][3])
                             : "r"(adr_h));
                uint32_t adr_l = (uint32_t)__cvta_generic_to_shared(
                    &Al[warp_m * 32 + im * 16 + (lane & 15)][kk + ((lane >> 4) << 3)]);
                asm volatile("ldmatrix.sync.aligned.m8n8.x4.shared.b16 {%0,%1,%2,%3}, [%4];"
                             : "=r"(al[im][0]), "=r"(al[im][1]), "=r"(al[im][2]), "=r"(al[im][3])
                             : "r"(adr_l));
            }
#pragma unroll
            for (int jn = 0; jn < 8; jn++) {
                int nb = warp_n * 64 + jn * 8;
                uint32_t bh[2], bl[2];
                uint32_t adr_bh = (uint32_t)__cvta_generic_to_shared(
                    &Bh[nb + (lane & 7)][kk + (((lane >> 3) & 1) << 3)]);
                asm volatile("ldmatrix.sync.aligned.m8n8.x2.shared.b16 {%0,%1}, [%2];"
                             : "=r"(bh[0]), "=r"(bh[1]) : "r"(adr_bh));
                uint32_t adr_bl = (uint32_t)__cvta_generic_to_shared(
                    &Bl[nb + (lane & 7)][kk + (((lane >> 3) & 1) << 3)]);
                asm volatile("ldmatrix.sync.aligned.m8n8.x2.shared.b16 {%0,%1}, [%2];"
                             : "=r"(bl[0]), "=r"(bl[1]) : "r"(adr_bl));
#pragma unroll
                for (int im = 0; im < 2; im++) {
                    float* c = acc[im][jn];
                    asm volatile(
                        "mma.sync.aligned.m16n8k16.row.col.f32.bf16.bf16.f32 "
                        "{%0,%1,%2,%3}, {%4,%5,%6,%7}, {%8,%9}, {%0,%1,%2,%3};"
                        : "+f"(c[0]), "+f"(c[1]), "+f"(c[2]), "+f"(c[3])
                        : "r"(ah[im][0]), "r"(ah[im][1]), "r"(ah[im][2]), "r"(ah[im][3]),
                          "r"(bh[0]), "r"(bh[1]));
                    asm volatile(
                        "mma.sync.aligned.m16n8k16.row.col.f32.bf16.bf16.f32 "
                        "{%0,%1,%2,%3}, {%4,%5,%6,%7}, {%8,%9}, {%0,%1,%2,%3};"
                        : "+f"(c[0]), "+f"(c[1]), "+f"(c[2]), "+f"(c[3])
                        : "r"(ah[im][0]), "r"(ah[im][1]), "r"(ah[im][2]), "r"(ah[im][3]),
                          "r"(bl[0]), "r"(bl[1]));
                    asm volatile(
                        "mma.sync.aligned.m16n8k16.row.col.f32.bf16.bf16.f32 "
                        "{%0,%1,%2,%3}, {%4,%5,%6,%7}, {%8,%9}, {%0,%1,%2,%3};"
                        : "+f"(c[0]), "+f"(c[1]), "+f"(c[2]), "+f"(c[3])
                        : "r"(al[im][0]), "r"(al[im][1]), "r"(al[im][2]), "r"(al[im][3]),
                          "r"(bh[0]), "r"(bh[1]));
                }
            }
        }
        __syncthreads();
    }

    // ---- epilogue: store feat (fp16), compute el/er per (row, head) ----
    int quad = lane >> 2, tc = lane & 3;
    float pel[2][2][2], per[2][2][2];   // [im][rowhalf][headhalf]
#pragma unroll
    for (int im = 0; im < 2; im++)
#pragma unroll
        for (int rh = 0; rh < 2; rh++)
#pragma unroll
            for (int hh = 0; hh < 2; hh++) { pel[im][rh][hh] = 0.f; per[im][rh][hh] = 0.f; }

#pragma unroll
    for (int im = 0; im < 2; im++) {
        int rowA = row0 + warp_m * 32 + im * 16 + quad;
#pragma unroll
        for (int jn = 0; jn < 8; jn++) {
            int col = warp_n * 64 + jn * 8 + tc * 2;
            int hh = jn >> 2;
            float* c = acc[im][jn];
            float a0 = attn_l[col], a1 = attn_l[col + 1];
            float b0 = attn_r[col], b1 = attn_r[col + 1];
            pel[im][0][hh] += c[0] * a0 + c[1] * a1;
            per[im][0][hh] += c[0] * b0 + c[1] * b1;
            pel[im][1][hh] += c[2] * a0 + c[3] * a1;
            per[im][1][hh] += c[2] * b0 + c[3] * b1;
            if (rowA < NN)
                *reinterpret_cast<__half2*>(&g_feat_h[(size_t)rowA * HC + col]) =
                    __floats2half2_rn(c[0], c[1]);
            if (rowA + 8 < NN)
                *reinterpret_cast<__half2*>(&g_feat_h[(size_t)(rowA + 8) * HC + col]) =
                    __floats2half2_rn(c[2], c[3]);
        }
    }
#pragma unroll
    for (int im = 0; im < 2; im++)
#pragma unroll
        for (int rh = 0; rh < 2; rh++)
#pragma unroll
            for (int hh = 0; hh < 2; hh++) {
                float e = pel[im][rh][hh], r = per[im][rh][hh];
                e += __shfl_xor_sync(0xffffffffu, e, 1);
                e += __shfl_xor_sync(0xffffffffu, e, 2);
                r += __shfl_xor_sync(0xffffffffu, r, 1);
                r += __shfl_xor_sync(0xffffffffu, r, 2);
                if (tc == 0) {
                    int row = row0 + warp_m * 32 + im * 16 + quad + rh * 8;
                    int head = warp_n * 2 + hh;
                    if (row < NN) {
                        g_el[row * HH + head] = e;
                        g_er[row * HH + head] = r;
                    }
                }
            }
}

// ---------------- CSR build ----------------
__global__ void zero_deg_kernel() {
    int i = blockIdx.x * blockDim.x + threadIdx.x;
    if (i < NN) g_deg[i] = 0;
}

__global__ void histo_kernel(const int* __restrict__ dst) {
    int e = blockIdx.x * blockDim.x + threadIdx.x;
    if (e < EE) atomicAdd(&g_deg[dst[e]], 1);
}

__global__ __launch_bounds__(1024) void scan1_kernel() {
    __shared__ int sh[1024];
    int i = blockIdx.x * 1024 + threadIdx.x;
    int v = (i < NN) ? g_deg[i] : 0;
    sh[threadIdx.x] = v;
    __syncthreads();
#pragma unroll
    for (int off = 1; off < 1024; off <<= 1) {
        int t = (threadIdx.x >= off) ? sh[threadIdx.x - off] : 0;
        __syncthreads();
        sh[threadIdx.x] += t;
        __syncthreads();
    }
    if (i < NN) g_rowoff[i] = sh[threadIdx.x] - v;        // exclusive
    if (threadIdx.x == 1023) g_blocksums[blockIdx.x] = sh[1023];
}

__global__ void scan2_kernel() {
    __shared__ int sh[128];
    int v = (threadIdx.x < NB) ? g_blocksums[threadIdx.x] : 0;
    sh[threadIdx.x] = v;
    __syncthreads();
#pragma unroll
    for (int off = 1; off < 128; off <<= 1) {
        int t = (threadIdx.x >= off) ? sh[threadIdx.x - off] : 0;
        __syncthreads();
        sh[threadIdx.x] += t;
        __syncthreads();
    }
    if (threadIdx.x < NB) g_blocksums[threadIdx.x] = sh[threadIdx.x] - v;  // exclusive
}

__global__ __launch_bounds__(1024) void scan3_kernel() {
    int i = blockIdx.x * 1024 + threadIdx.x;
    if (i < NN) {
        int v = g_rowoff[i] + g_blocksums[blockIdx.x];
        g_rowoff[i] = v;
        g_cursor[i] = v;
    }
    if (i == 0) g_rowoff[NN] = EE;
}

__global__ void scatter_kernel(const int* __restrict__ src,
                               const int* __restrict__ dst) {
    int e = blockIdx.x * blockDim.x + threadIdx.x;
    if (e >= EE) return;
    int pos = atomicAdd(&g_cursor[dst[e]], 1);
    g_srcsorted[pos] = src[e];
}

// ------- fused single-pass softmax-aggregate + head-mean + relu -------
// One warp per dst node. Key identity: out = (sum ex_j * f_j) / (sum ex_j),
// so numerator and denominator accumulate in ONE pass over edges.
// Per 32-edge chunk: lanes compute their edge's 4 head-exps once (parked in
// smem), then the warp sweeps the chunk gathering fp16 feat rows.
__global__ __launch_bounds__(256) void aggregate_fused_kernel(
    const float* __restrict__ bias, float* __restrict__ out)
{
    __shared__ float sh_ex[8][32][4];   // [warp][edge-in-chunk][head]
    int wslot = threadIdx.x >> 5;
    int warp = (blockIdx.x * blockDim.x + threadIdx.x) >> 5;
    int lane = threadIdx.x & 31;
    if (warp >= NN) return;
    int n = warp;
    int head = lane >> 3;

    int start = g_rowoff[n];
    int end   = g_rowoff[n + 1];

    float4 er4 = *reinterpret_cast<const float4*>(&g_er[n * HH]);

    float4 den = make_float4(0.f, 0.f, 0.f, 0.f);   // per-lane partials
    float4 acc = make_float4(0.f, 0.f, 0.f, 0.f);   // unnormalized numerator
    const uint2* feat2 = reinterpret_cast<const uint2*>(g_feat_h);

    for (int j0 = start; j0 < end; j0 += 32) {
        int jj = j0 + lane;
        int sj = 0;
        float4 ex4 = make_float4(0.f, 0.f, 0.f, 0.f);
        if (jj < end) {
            sj = g_srcsorted[jj];
            float4 el4 = *reinterpret_cast<const float4*>(&g_el[sj * HH]);
            float v0 = el4.x + er4.x, v1 = el4.y + er4.y;
            float v2 = el4.z + er4.z, v3 = el4.w + er4.w;
            v0 = v0 > 0.f ? v0 : 0.2f * v0;
            v1 = v1 > 0.f ? v1 : 0.2f * v1;
            v2 = v2 > 0.f ? v2 : 0.2f * v2;
            v3 = v3 > 0.f ? v3 : 0.2f * v3;
            ex4 = make_float4(__expf(v0), __expf(v1), __expf(v2), __expf(v3));
            den.x += ex4.x; den.y += ex4.y; den.z += ex4.z; den.w += ex4.w;
        }
        *reinterpret_cast<float4*>(&sh_ex[wslot][lane][0]) = ex4;
        __syncwarp();
        int m = end - j0; if (m > 32) m = 32;
        for (int t = 0; t < m; t++) {
            int s = __shfl_sync(0xffffffffu, sj, t);
            float num = sh_ex[wslot][t][head];          // broadcast LDS
            uint2 u = feat2[(size_t)s * 32 + lane];     // 8B fp16 gather
            float2 f01 = __half22float2(*reinterpret_cast<__half2*>(&u.x));
            float2 f23 = __half22float2(*reinterpret_cast<__half2*>(&u.y));
            acc.x += num * f01.x; acc.y += num * f01.y;
            acc.z += num * f23.x; acc.w += num * f23.y;
        }
        __syncwarp();
    }

    // reduce denominator partials across warp (all 4 heads)
#pragma unroll
    for (int off = 16; off > 0; off >>= 1) {
        den.x += __shfl_xor_sync(0xffffffffu, den.x, off);
        den.y += __shfl_xor_sync(0xffffffffu, den.y, off);
        den.z += __shfl_xor_sync(0xffffffffu, den.z, off);
        den.w += __shfl_xor_sync(0xffffffffu, den.w, off);
    }
    float dmine = (head == 0) ? den.x : (head == 1) ? den.y
                 : (head == 2) ? den.z : den.w;
    float rinv = (dmine > 0.f) ? __fdividef(1.f, dmine) : 0.f;
    acc.x *= rinv; acc.y *= rinv; acc.z *= rinv; acc.w *= rinv;

    // head mean: sum over lane-groups differing in bits 3,4
#pragma unroll
    for (int off = 8; off <= 16; off <<= 1) {
        acc.x += __shfl_xor_sync(0xffffffffu, acc.x, off);
        acc.y += __shfl_xor_sync(0xffffffffu, acc.y, off);
        acc.z += __shfl_xor_sync(0xffffffffu, acc.z, off);
        acc.w += __shfl_xor_sync(0xffffffffu, acc.w, off);
    }
    if (lane < 8) {
        float bs[4] = {0.f, 0.f, 0.f, 0.f};
#pragma unroll
        for (int h = 0; h < HH; h++) {
#pragma unroll
            for (int k = 0; k < 4; k++) bs[k] += bias[h * CC + lane * 4 + k];
        }
        float4 o;
        o.x = fmaxf(0.25f * (acc.x + bs[0]), 0.f);
        o.y = fmaxf(0.25f * (acc.y + bs[1]), 0.f);
        o.z = fmaxf(0.25f * (acc.z + bs[2]), 0.f);
        o.w = fmaxf(0.25f * (acc.w + bs[3]), 0.f);
        reinterpret_cast<float4*>(out)[n * 8 + lane] = o;
    }
}

// ---------------- launch: CSR build forked onto side stream ----------------
extern "C" void kernel_launch(void* const* d_in, const int* in_sizes, int n_in,
                              void* d_out, int out_size)
{
    const float* x      = (const float*)d_in[0];
    const int*   src    = (const int*)d_in[1];
    const int*   dst    = (const int*)d_in[2];
    const float* W      = (const float*)d_in[3];
    const float* attn_l = (const float*)d_in[4];
    const float* attn_r = (const float*)d_in[5];
    const float* bias   = (const float*)d_in[6];
    float* out = (float*)d_out;

    // one-time host resources (created on the pre-capture correctness call)
    static cudaStream_t s2 = nullptr;
    static cudaEvent_t evFork = nullptr, evJoin = nullptr;
    static bool ok2 = false;
    if (!evFork) {
        ok2 = (cudaStreamCreateWithFlags(&s2, cudaStreamNonBlocking) == cudaSuccess);
        cudaEventCreateWithFlags(&evFork, cudaEventDisableTiming);
        cudaEventCreateWithFlags(&evJoin, cudaEventDisableTiming);
    }
    cudaStream_t sb = ok2 ? s2 : (cudaStream_t)0;

    if (ok2) {
        cudaEventRecord(evFork, 0);
        cudaStreamWaitEvent(s2, evFork, 0);
    }

    // CSR chain (side stream)
    zero_deg_kernel<<<(NN + 255) / 256, 256, 0, sb>>>();
    histo_kernel<<<(EE + 255) / 256, 256, 0, sb>>>(dst);
    scan1_kernel<<<NB, 1024, 0, sb>>>();
    scan2_kernel<<<1, 128, 0, sb>>>();
    scan3_kernel<<<NB, 1024, 0, sb>>>();
    scatter_kernel<<<(EE + 255) / 256, 256, 0, sb>>>(src, dst);

    // GEMM chain (main stream)
    wprep_kernel<<<(IN_F * HC + 255) / 256, 256>>>(W);
    gemm_feat_tc_kernel<<<(NN + 127) / 128, 256>>>(x, attn_l, attn_r);

    if (ok2) {
        cudaEventRecord(evJoin, s2);
        cudaStreamWaitEvent(0, evJoin, 0);
    }

    aggregate_fused_kernel<<<(NN * 32 + 255) / 256, 256>>>(bias, out);
}